// round 11
// baseline (speedup 1.0000x reference)
#include <cuda_runtime.h>
#include <cuda_bf16.h>
#include <mma.h>
#include <math.h>
#include <stdint.h>

using namespace nvcuda;

// Problem constants
#define BATCH 64
#define NATOM 512
#define DFEAT 128
#define DIMP  128
#define MROWS (BATCH * NATOM)      // 32768
#define NCOLS (2 * DIMP)           // 256 (q | k fused in n)
#define TILE_M 64
#define NTILES (MROWS / TILE_M)    // 512 m-tiles (8 per batch)

// smem strides (elements)
#define ASTRIDE 40                 // 32 + 8 pad (bf16)
#define BSTRIDE 264                // 256 + 8 pad (bf16)
#define QSTRIDE 132                // 128 + 4 pad (fp32)

// single-stage smem layout (bytes)
#define OFF_AH   0
#define OFF_AL   (TILE_M * ASTRIDE * 2)                 // 5120
#define OFF_BH   (OFF_AL + TILE_M * ASTRIDE * 2)        // 10240
#define OFF_BL   (OFF_BH + 32 * BSTRIDE * 2)            // 27136
#define STAGE_BYTES (OFF_BL + 32 * BSTRIDE * 2)         // 44032
#define EPI_BYTES (2 * TILE_M * QSTRIDE * 4)            // 67584 (Qs | Ks)
#define DSMEM_BYTES (EPI_BYTES > STAGE_BYTES ? EPI_BYTES : STAGE_BYTES)  // 67584

// Device scratch
__device__ __align__(16) __nv_bfloat16 g_Bhl[2][DFEAT][NCOLS];  // Bh, Bl (128 KB)
__device__ float g_Kt[BATCH][DIMP][NATOM];             // K transposed, 16 MB
__device__ float g_qsum_part[NTILES][DIMP];            // 256 KB
__device__ float g_diag[MROWS];                        // 128 KB

// ---------------------------------------------------------------------------
// convertB: Wq|Wk fp32 -> g_Bhl (hi, lo bf16)
// ---------------------------------------------------------------------------
__global__ __launch_bounds__(256)
void convertB_kernel(const float* __restrict__ Wq, const float* __restrict__ Wk) {
    int idx = blockIdx.x * blockDim.x + threadIdx.x;   // < 8192
    int k  = idx >> 6;
    int n4 = (idx & 63) << 2;

    float4 w = (n4 < DIMP)
        ? *(const float4*)(Wq + (size_t)k * DIMP + n4)
        : *(const float4*)(Wk + (size_t)k * DIMP + (n4 - DIMP));

    float v[4] = {w.x, w.y, w.z, w.w};
    uint16_t h[4], l[4];
    #pragma unroll
    for (int i = 0; i < 4; i++) {
        __nv_bfloat16 hb = __float2bfloat16(v[i]);
        __nv_bfloat16 lb = __float2bfloat16(v[i] - __bfloat162float(hb));
        h[i] = __bfloat16_as_ushort(hb);
        l[i] = __bfloat16_as_ushort(lb);
    }
    *(uint2*)(&g_Bhl[0][k][n4]) = make_uint2(((uint32_t)h[1] << 16) | h[0],
                                             ((uint32_t)h[3] << 16) | h[2]);
    *(uint2*)(&g_Bhl[1][k][n4]) = make_uint2(((uint32_t)l[1] << 16) | l[0],
                                             ((uint32_t)l[3] << 16) | l[2]);
}

// ---------------------------------------------------------------------------
// Fused GEMM: 512 CTAs x 256 threads, 2 CTAs/SM. Tile 64m x 256n, 3xbf16 split.
// Plain LDG->reg->STS loading; cross-CTA overlap hides load/convert latency.
// Epilogue: writes K^T, qsum partials, diag. Q never hits global memory.
// ---------------------------------------------------------------------------
__global__ __launch_bounds__(256, 2)
void gemm_fused_kernel(const float* __restrict__ A,
                       const float* __restrict__ bq, const float* __restrict__ bk,
                       const float* __restrict__ mask) {
    extern __shared__ char dsm[];
    __shared__ float maskS[TILE_M];
    __shared__ float partQ[2][DIMP];

    const int tid  = threadIdx.x;
    const int warp = tid >> 5;
    const int lane = tid & 31;
    const int mt   = blockIdx.x;
    const int bm   = mt * TILE_M;
    const int wm   = (warp >> 2) * 32;     // 2 warp-rows of 32
    const int wn   = (warp & 3) * 64;      // 4 warp-cols of 64

    // --- accumulator init with bias (replicated 16-row tile in dsm) ---
    float* biasT = (float*)dsm;            // 16 x 256
    for (int i = tid; i < 16 * NCOLS; i += 256) {
        int col = i & 255;
        biasT[i] = (col < DIMP) ? bq[col] : bk[col - DIMP];
    }
    __syncthreads();

    wmma::fragment<wmma::accumulator, 16, 16, 16, float> acc[2][4];
    #pragma unroll
    for (int i = 0; i < 2; i++)
        #pragma unroll
        for (int j = 0; j < 4; j++)
            wmma::load_matrix_sync(acc[i][j], biasT + wn + j * 16, NCOLS, wmma::mem_row_major);
    __syncthreads();

    // A loader indices: 64x32 fp32 = 512 float4, 2 per thread
    const int ar0 = tid >> 3,          ac0 = (tid & 7) * 4;
    const int ar1 = (tid + 256) >> 3,  ac1 = ((tid + 256) & 7) * 4;
    // B loader indices: 1024 x 16B per matrix, 4 per thread
    int brow[4], bo16[4];
    #pragma unroll
    for (int v = 0; v < 4; v++) {
        int c = tid + v * 256;
        brow[v] = c >> 5;
        bo16[v] = (c & 31) * 16;
    }

    __nv_bfloat16* AhS = (__nv_bfloat16*)(dsm + OFF_AH);
    __nv_bfloat16* AlS = (__nv_bfloat16*)(dsm + OFF_AL);
    char* BhS = dsm + OFF_BH;
    char* BlS = dsm + OFF_BL;

    float4 paA[2], paB[2];
    // prologue A fetch (chunk 0)
    paA[0] = *(const float4*)(A + (size_t)(bm + ar0) * DFEAT + ac0);
    paA[1] = *(const float4*)(A + (size_t)(bm + ar1) * DFEAT + ac1);

    for (int kc = 0; kc < 4; kc++) {
        // issue B LDGs for this chunk
        uint4 rbh[4], rbl[4];
        #pragma unroll
        for (int v = 0; v < 4; v++) {
            rbh[v] = *(const uint4*)((const char*)&g_Bhl[0][kc * 32 + brow[v]][0] + bo16[v]);
            rbl[v] = *(const uint4*)((const char*)&g_Bhl[1][kc * 32 + brow[v]][0] + bo16[v]);
        }
        // prefetch next chunk's A
        if (kc < 3) {
            paB[0] = *(const float4*)(A + (size_t)(bm + ar0) * DFEAT + (kc + 1) * 32 + ac0);
            paB[1] = *(const float4*)(A + (size_t)(bm + ar1) * DFEAT + (kc + 1) * 32 + ac1);
        }
        // convert current A (overlaps in-flight LDGs)
        #pragma unroll
        for (int v = 0; v < 2; v++) {
            float vv[4] = {paA[v].x, paA[v].y, paA[v].z, paA[v].w};
            uint16_t h[4], l[4];
            #pragma unroll
            for (int i = 0; i < 4; i++) {
                __nv_bfloat16 hb = __float2bfloat16(vv[i]);
                __nv_bfloat16 lb = __float2bfloat16(vv[i] - __bfloat162float(hb));
                h[i] = __bfloat16_as_ushort(hb);
                l[i] = __bfloat16_as_ushort(lb);
            }
            int r = v ? ar1 : ar0, c = v ? ac1 : ac0;
            *(uint2*)(&AhS[r * ASTRIDE + c]) =
                make_uint2(((uint32_t)h[1] << 16) | h[0], ((uint32_t)h[3] << 16) | h[2]);
            *(uint2*)(&AlS[r * ASTRIDE + c]) =
                make_uint2(((uint32_t)l[1] << 16) | l[0], ((uint32_t)l[3] << 16) | l[2]);
        }
        // land B into smem
        #pragma unroll
        for (int v = 0; v < 4; v++) {
            *(uint4*)(BhS + brow[v] * (BSTRIDE * 2) + bo16[v]) = rbh[v];
            *(uint4*)(BlS + brow[v] * (BSTRIDE * 2) + bo16[v]) = rbl[v];
        }
        __syncthreads();

        // MMA: 3 passes (Ah*Bh, Al*Bh, Ah*Bl), 2 k-steps each
        #pragma unroll
        for (int pass = 0; pass < 3; pass++) {
            const __nv_bfloat16* Ap = (pass == 1) ? AlS : AhS;
            const __nv_bfloat16* Bp = (const __nv_bfloat16*)((pass == 2) ? BlS : BhS);
            #pragma unroll
            for (int kk = 0; kk < 32; kk += 16) {
                wmma::fragment<wmma::matrix_a, 16, 16, 16, __nv_bfloat16, wmma::row_major> af[2];
                wmma::fragment<wmma::matrix_b, 16, 16, 16, __nv_bfloat16, wmma::row_major> bf[4];
                #pragma unroll
                for (int i = 0; i < 2; i++)
                    wmma::load_matrix_sync(af[i], Ap + (wm + i * 16) * ASTRIDE + kk, ASTRIDE);
                #pragma unroll
                for (int j = 0; j < 4; j++)
                    wmma::load_matrix_sync(bf[j], Bp + kk * BSTRIDE + wn + j * 16, BSTRIDE);
                #pragma unroll
                for (int i = 0; i < 2; i++)
                    #pragma unroll
                    for (int j = 0; j < 4; j++)
                        wmma::mma_sync(acc[i][j], af[i], bf[j], acc[i][j]);
            }
        }
        __syncthreads();

        paA[0] = paB[0];
        paA[1] = paB[1];
    }

    // --- epilogue: overlay Qs|Ks in dsm ---
    float* Qs = (float*)dsm;                       // 64 x QSTRIDE
    float* Ks = Qs + TILE_M * QSTRIDE;
    #pragma unroll
    for (int i = 0; i < 2; i++) {
        #pragma unroll
        for (int j = 0; j < 4; j++) {
            int n = wn + j * 16;
            float* t = (n < DIMP) ? (Qs + (wm + i * 16) * QSTRIDE + n)
                                  : (Ks + (wm + i * 16) * QSTRIDE + (n - DIMP));
            wmma::store_matrix_sync(t, acc[i][j], QSTRIDE, wmma::mem_row_major);
        }
    }
    if (tid < TILE_M) maskS[tid] = mask[(size_t)bm + tid];
    __syncthreads();

    // K^T write: batch b, atom slot ns..ns+63. Coalesced stores per d-row.
    {
        const int b = mt >> 3, ns = (mt & 7) * TILE_M;
        #pragma unroll
        for (int v = 0; v < 8; v++) {
            int f = v * 256 + tid;        // 0..2047
            int n = f & 63;
            int d4 = (f >> 6) * 4;        // 0..124
            float4 kv = *(float4*)(&Ks[n * QSTRIDE + d4]);
            g_Kt[b][d4 + 0][ns + n] = kv.x;
            g_Kt[b][d4 + 1][ns + n] = kv.y;
            g_Kt[b][d4 + 2][ns + n] = kv.z;
            g_Kt[b][d4 + 3][ns + n] = kv.w;
        }
    }

    // qsum partial: 2 row-groups of 32
    {
        const int d = tid & 127, h = tid >> 7;
        float acc_q = 0.0f;
        #pragma unroll 8
        for (int n = h * 32; n < h * 32 + 32; n++)
            acc_q += maskS[n] * Qs[n * QSTRIDE + d];
        partQ[h][d] = acc_q;
    }
    __syncthreads();
    if (tid < DIMP)
        g_qsum_part[mt][tid] = partQ[0][tid] + partQ[1][tid];

    // diag[n] = q[n] . k[n]  (8 warps x 8 rows)
    #pragma unroll
    for (int rr = 0; rr < 8; rr++) {
        const int n = warp * 8 + rr;
        const float4 q4 = *(const float4*)(&Qs[n * QSTRIDE + lane * 4]);
        const float4 k4 = *(const float4*)(&Ks[n * QSTRIDE + lane * 4]);
        float s = q4.x * k4.x + q4.y * k4.y + q4.z * k4.z + q4.w * k4.w;
        #pragma unroll
        for (int o = 16; o; o >>= 1) s += __shfl_down_sync(0xffffffffu, s, o);
        if (lane == 0) g_diag[(size_t)bm + n] = s;
    }
}

// ---------------------------------------------------------------------------
// Block reductions (512 threads, 16 warps)
// ---------------------------------------------------------------------------
__device__ __forceinline__ float block_reduce_sum(float v, float* red) {
    int lane = threadIdx.x & 31, warp = threadIdx.x >> 5;
    #pragma unroll
    for (int o = 16; o; o >>= 1) v += __shfl_down_sync(0xffffffffu, v, o);
    if (lane == 0) red[warp] = v;
    __syncthreads();
    if (warp == 0) {
        v = (lane < 16) ? red[lane] : 0.0f;
        #pragma unroll
        for (int o = 8; o; o >>= 1) v += __shfl_down_sync(0xffffffffu, v, o);
        if (lane == 0) red[16] = v;
    }
    __syncthreads();
    float r = red[16];
    __syncthreads();
    return r;
}

__device__ __forceinline__ float block_reduce_max(float v, float* red) {
    int lane = threadIdx.x & 31, warp = threadIdx.x >> 5;
    #pragma unroll
    for (int o = 16; o; o >>= 1) v = fmaxf(v, __shfl_down_sync(0xffffffffu, v, o));
    if (lane == 0) red[warp] = v;
    __syncthreads();
    if (warp == 0) {
        v = (lane < 16) ? red[lane] : -INFINITY;
        #pragma unroll
        for (int o = 8; o; o >>= 1) v = fmaxf(v, __shfl_down_sync(0xffffffffu, v, o));
        if (lane == 0) red[16] = v;
    }
    __syncthreads();
    float r = red[16];
    __syncthreads();
    return r;
}

// ---------------------------------------------------------------------------
// attn_fused: grid BATCH, 512 threads. agg -> normalize -> softmax -> context.
// ---------------------------------------------------------------------------
__global__ __launch_bounds__(512)
void attn_fused_kernel(const float* __restrict__ mask, float* __restrict__ out) {
    const int b = blockIdx.x, tid = threadIdx.x;
    const int lane = tid & 31, warp = tid >> 5;
    __shared__ float qs[DIMP];
    __shared__ float aw[NATOM];
    __shared__ float red[17];

    if (tid < DIMP) {
        float a = 0.0f;
        #pragma unroll
        for (int p = 0; p < 8; p++) a += g_qsum_part[b * 8 + p][tid];
        qs[tid] = a;
    }
    __syncthreads();

    const float* __restrict__ Kt = &g_Kt[b][0][0];   // [128][512]

    // agg[n] = mask[n] * (k[n].qsum - diag[n]); thread-per-atom, coalesced
    float acc = 0.0f;
    #pragma unroll 8
    for (int d = 0; d < DIMP; d++)
        acc = fmaf(Kt[d * NATOM + tid], qs[d], acc);
    const float mv = mask[(size_t)b * NATOM + tid];
    const float v = mv * (acc - g_diag[(size_t)b * NATOM + tid]);

    // normalize over atoms, masked softmax
    const float total = block_reduce_sum(v * v, red);
    const float nrm = sqrtf(total);
    const float x = v / nrm + (1.0f - mv) * (-1e9f);
    const float mx = block_reduce_max(x, red);
    const float e = expf(x - mx);
    const float denom = block_reduce_sum(e, red);
    const float attn = e / denom;
    out[(size_t)b * NATOM + tid] = attn;
    aw[tid] = attn * mv;
    __syncthreads();

    // context[d] = sum_n aw[n] * Kt[d][n]; warp-per-d-row, contiguous rows
    #pragma unroll
    for (int r = 0; r < 8; r++) {
        const int d = warp * 8 + r;
        const float* row = Kt + d * NATOM;
        float s = 0.0f;
        #pragma unroll
        for (int j = 0; j < 4; j++) {
            const float4 k4 = *(const float4*)(row + j * 128 + lane * 4);
            const float4 a4 = *(const float4*)(&aw[j * 128 + lane * 4]);
            s += k4.x * a4.x + k4.y * a4.y + k4.z * a4.z + k4.w * a4.w;
        }
        #pragma unroll
        for (int o = 16; o; o >>= 1) s += __shfl_down_sync(0xffffffffu, s, o);
        if (lane == 0) out[(size_t)BATCH * NATOM + (size_t)b * DIMP + d] = s;
    }
}

// ---------------------------------------------------------------------------
extern "C" void kernel_launch(void* const* d_in, const int* in_sizes, int n_in,
                              void* d_out, int out_size) {
    const float* atom_query = (const float*)d_in[0];
    const float* mask       = (const float*)d_in[1];
    const float* Wq         = (const float*)d_in[2];
    const float* bq         = (const float*)d_in[3];
    const float* Wk         = (const float*)d_in[4];
    const float* bk         = (const float*)d_in[5];
    float* out = (float*)d_out;

    static int smem_set = 0;
    if (!smem_set) {
        cudaFuncSetAttribute(gemm_fused_kernel,
                             cudaFuncAttributeMaxDynamicSharedMemorySize, DSMEM_BYTES);
        smem_set = 1;
    }

    convertB_kernel<<<32, 256>>>(Wq, Wk);
    gemm_fused_kernel<<<NTILES, 256, DSMEM_BYTES>>>(atom_query, bq, bk, mask);
    attn_fused_kernel<<<BATCH, 512>>>(mask, out);
}

// round 12
// speedup vs baseline: 1.5777x; 1.5777x over previous
#include <cuda_runtime.h>
#include <cuda_bf16.h>
#include <mma.h>
#include <math.h>
#include <stdint.h>

using namespace nvcuda;

// Problem constants
#define BATCH 64
#define NATOM 512
#define DFEAT 128
#define DIMP  128
#define MROWS (BATCH * NATOM)      // 32768
#define NCOLS (2 * DIMP)           // 256 (q | k fused in n)
#define NTILES (MROWS / 128)       // 256 m-tiles (4 per batch)

// smem strides (elements)
#define ASTRIDE 40                 // 32 + 8 pad (bf16)
#define BSTRIDE 264                // 256 + 8 pad (bf16)
#define QSTRIDE 132                // 128 + 4 pad (fp32)

// stage layout (bytes, per buffer)
#define OFF_AH   0
#define OFF_AL   (128 * ASTRIDE * 2)                    // 10240
#define OFF_BH   (OFF_AL + 128 * ASTRIDE * 2)           // 20480
#define OFF_BL   (OFF_BH + 32 * BSTRIDE * 2)            // 37376
#define STAGE_BYTES (OFF_BL + 32 * BSTRIDE * 2)         // 54272
#define EPI_BYTES (2 * 128 * QSTRIDE * 4)               // 135168 (Qs | Ks)
#define PIPE_BYTES (2 * STAGE_BYTES)                    // 108544
#define DSMEM_BYTES (EPI_BYTES > PIPE_BYTES ? EPI_BYTES : PIPE_BYTES)

// Device scratch
__device__ float g_Kt[BATCH][DIMP][NATOM];             // K transposed, 16 MB
__device__ float g_qsum_part[NTILES][DIMP];            // 128 KB
__device__ float g_diag[MROWS];                        // 128 KB

// ---------------------------------------------------------------------------
// Fused GEMM (round-8 proven version): 256 CTAs x 512 threads.
// Tile 128m x 256n, K=3x128 bf16 split, double-buffered k-chunks,
// W converted in-loader. Epilogue: K^T, qsum partials, diag.
// ---------------------------------------------------------------------------
__global__ __launch_bounds__(512, 1)
void gemm_fused_kernel(const float* __restrict__ A,
                       const float* __restrict__ Wq, const float* __restrict__ Wk,
                       const float* __restrict__ bq, const float* __restrict__ bk,
                       const float* __restrict__ mask) {
    extern __shared__ char dsm[];
    __shared__ float maskS[128];
    __shared__ float partQ[4][DIMP];

    const int tid  = threadIdx.x;
    const int warp = tid >> 5;
    const int lane = tid & 31;
    const int mt   = blockIdx.x;
    const int bm   = mt * 128;
    const int wm   = (warp >> 2) * 32;     // 4 warp-rows of 32
    const int wn   = (warp & 3) * 64;      // 4 warp-cols of 64

    // --- accumulator init with bias (replicated 16-row tile in dsm) ---
    float* biasT = (float*)dsm;            // 16 x 256
    for (int i = tid; i < 16 * NCOLS; i += 512) {
        int col = i & 255;
        biasT[i] = (col < DIMP) ? bq[col] : bk[col - DIMP];
    }
    __syncthreads();

    wmma::fragment<wmma::accumulator, 16, 16, 16, float> acc[2][4];
    #pragma unroll
    for (int i = 0; i < 2; i++)
        #pragma unroll
        for (int j = 0; j < 4; j++)
            wmma::load_matrix_sync(acc[i][j], biasT + wn + j * 16, NCOLS, wmma::mem_row_major);
    __syncthreads();

    // loader index precompute
    const int ar0 = tid >> 3,          ac0 = (tid & 7) * 4;
    const int ar1 = (tid + 512) >> 3,  ac1 = ((tid + 512) & 7) * 4;
    int brr[4], bcc[4];
    #pragma unroll
    for (int v = 0; v < 4; v++) {
        int f = tid + v * 512;
        brr[v] = f >> 6;
        bcc[v] = (f & 63) * 4;
    }

    float4 pa[2], pb[4];
    #define FETCH(kc)                                                                   \
        do {                                                                            \
            pa[0] = *(const float4*)(A + (size_t)(bm + ar0) * DFEAT + (kc) * 32 + ac0); \
            pa[1] = *(const float4*)(A + (size_t)(bm + ar1) * DFEAT + (kc) * 32 + ac1); \
            _Pragma("unroll")                                                           \
            for (int v = 0; v < 4; v++) {                                               \
                int k = (kc) * 32 + brr[v];                                             \
                pb[v] = (bcc[v] < DIMP)                                                 \
                    ? *(const float4*)(Wq + (size_t)k * DIMP + bcc[v])                  \
                    : *(const float4*)(Wk + (size_t)k * DIMP + (bcc[v] - DIMP));        \
            }                                                                           \
        } while (0)

    #define CVT_STORE(buf)                                                              \
        do {                                                                            \
            __nv_bfloat16* AhS = (__nv_bfloat16*)(dsm + (buf) * STAGE_BYTES + OFF_AH);  \
            __nv_bfloat16* AlS = (__nv_bfloat16*)(dsm + (buf) * STAGE_BYTES + OFF_AL);  \
            __nv_bfloat16* BhS = (__nv_bfloat16*)(dsm + (buf) * STAGE_BYTES + OFF_BH);  \
            __nv_bfloat16* BlS = (__nv_bfloat16*)(dsm + (buf) * STAGE_BYTES + OFF_BL);  \
            _Pragma("unroll")                                                           \
            for (int v = 0; v < 2; v++) {                                               \
                float vv[4] = {pa[v].x, pa[v].y, pa[v].z, pa[v].w};                     \
                uint16_t h[4], l[4];                                                    \
                _Pragma("unroll")                                                       \
                for (int i = 0; i < 4; i++) {                                           \
                    __nv_bfloat16 hb = __float2bfloat16(vv[i]);                         \
                    __nv_bfloat16 lb = __float2bfloat16(vv[i] - __bfloat162float(hb));  \
                    h[i] = __bfloat16_as_ushort(hb);                                    \
                    l[i] = __bfloat16_as_ushort(lb);                                    \
                }                                                                       \
                int r = v ? ar1 : ar0, c = v ? ac1 : ac0;                               \
                *(uint2*)(&AhS[r * ASTRIDE + c]) =                                      \
                    make_uint2(((uint32_t)h[1] << 16) | h[0], ((uint32_t)h[3] << 16) | h[2]); \
                *(uint2*)(&AlS[r * ASTRIDE + c]) =                                      \
                    make_uint2(((uint32_t)l[1] << 16) | l[0], ((uint32_t)l[3] << 16) | l[2]); \
            }                                                                           \
            _Pragma("unroll")                                                           \
            for (int v = 0; v < 4; v++) {                                               \
                float vv[4] = {pb[v].x, pb[v].y, pb[v].z, pb[v].w};                     \
                uint16_t h[4], l[4];                                                    \
                _Pragma("unroll")                                                       \
                for (int i = 0; i < 4; i++) {                                           \
                    __nv_bfloat16 hb = __float2bfloat16(vv[i]);                         \
                    __nv_bfloat16 lb = __float2bfloat16(vv[i] - __bfloat162float(hb));  \
                    h[i] = __bfloat16_as_ushort(hb);                                    \
                    l[i] = __bfloat16_as_ushort(lb);                                    \
                }                                                                       \
                *(uint2*)(&BhS[brr[v] * BSTRIDE + bcc[v]]) =                            \
                    make_uint2(((uint32_t)h[1] << 16) | h[0], ((uint32_t)h[3] << 16) | h[2]); \
                *(uint2*)(&BlS[brr[v] * BSTRIDE + bcc[v]]) =                            \
                    make_uint2(((uint32_t)l[1] << 16) | l[0], ((uint32_t)l[3] << 16) | l[2]); \
            }                                                                           \
        } while (0)

    // --- pipelined mainloop: 4 chunks of k=32, 3 passes each ---
    FETCH(0);
    CVT_STORE(0);
    __syncthreads();

    #pragma unroll
    for (int kc = 0; kc < 4; kc++) {
        const int cur = kc & 1;
        if (kc < 3) FETCH(kc + 1);

        const __nv_bfloat16* AhS = (const __nv_bfloat16*)(dsm + cur * STAGE_BYTES + OFF_AH);
        const __nv_bfloat16* AlS = (const __nv_bfloat16*)(dsm + cur * STAGE_BYTES + OFF_AL);
        const __nv_bfloat16* BhS = (const __nv_bfloat16*)(dsm + cur * STAGE_BYTES + OFF_BH);
        const __nv_bfloat16* BlS = (const __nv_bfloat16*)(dsm + cur * STAGE_BYTES + OFF_BL);

        #pragma unroll
        for (int pass = 0; pass < 3; pass++) {
            const __nv_bfloat16* Ap = (pass == 1) ? AlS : AhS;
            const __nv_bfloat16* Bp = (pass == 2) ? BlS : BhS;
            #pragma unroll
            for (int kk = 0; kk < 32; kk += 16) {
                wmma::fragment<wmma::matrix_a, 16, 16, 16, __nv_bfloat16, wmma::row_major> af[2];
                wmma::fragment<wmma::matrix_b, 16, 16, 16, __nv_bfloat16, wmma::row_major> bf[4];
                #pragma unroll
                for (int i = 0; i < 2; i++)
                    wmma::load_matrix_sync(af[i], Ap + (wm + i * 16) * ASTRIDE + kk, ASTRIDE);
                #pragma unroll
                for (int j = 0; j < 4; j++)
                    wmma::load_matrix_sync(bf[j], Bp + kk * BSTRIDE + wn + j * 16, BSTRIDE);
                #pragma unroll
                for (int i = 0; i < 2; i++)
                    #pragma unroll
                    for (int j = 0; j < 4; j++)
                        wmma::mma_sync(acc[i][j], af[i], bf[j], acc[i][j]);
            }
        }

        if (kc < 3) CVT_STORE(1 - cur);
        __syncthreads();
    }

    // --- epilogue: overlay Qs|Ks in dsm ---
    float* Qs = (float*)dsm;                       // 128 x QSTRIDE
    float* Ks = Qs + 128 * QSTRIDE;
    #pragma unroll
    for (int i = 0; i < 2; i++) {
        #pragma unroll
        for (int j = 0; j < 4; j++) {
            int n = wn + j * 16;
            float* t = (n < DIMP) ? (Qs + (wm + i * 16) * QSTRIDE + n)
                                  : (Ks + (wm + i * 16) * QSTRIDE + (n - DIMP));
            wmma::store_matrix_sync(t, acc[i][j], QSTRIDE, wmma::mem_row_major);
        }
    }
    if (tid < 128) maskS[tid] = mask[(size_t)bm + tid];
    __syncthreads();

    // K^T write: batch b, atom slot ns..ns+127. Coalesced stores per d-row.
    {
        const int b = mt >> 2, ns = (mt & 3) * 128;
        #pragma unroll
        for (int v = 0; v < 8; v++) {
            int f = v * 512 + tid;        // 0..4095
            int n = f & 127;
            int d4 = (f >> 7) * 4;        // 0..124
            float4 kv = *(float4*)(&Ks[n * QSTRIDE + d4]);
            g_Kt[b][d4 + 0][ns + n] = kv.x;
            g_Kt[b][d4 + 1][ns + n] = kv.y;
            g_Kt[b][d4 + 2][ns + n] = kv.z;
            g_Kt[b][d4 + 3][ns + n] = kv.w;
        }
    }

    // qsum partial: 4 row-groups of 32
    {
        const int d = tid & 127, h = tid >> 7;
        float acc_q = 0.0f;
        #pragma unroll 8
        for (int n = h * 32; n < h * 32 + 32; n++)
            acc_q += maskS[n] * Qs[n * QSTRIDE + d];
        partQ[h][d] = acc_q;
    }
    __syncthreads();
    if (tid < DIMP)
        g_qsum_part[mt][tid] = partQ[0][tid] + partQ[1][tid] + partQ[2][tid] + partQ[3][tid];

    // diag[n] = q[n] . k[n]  (16 warps x 8 rows)
    #pragma unroll
    for (int rr = 0; rr < 8; rr++) {
        const int n = warp * 8 + rr;
        const float4 q4 = *(const float4*)(&Qs[n * QSTRIDE + lane * 4]);
        const float4 k4 = *(const float4*)(&Ks[n * QSTRIDE + lane * 4]);
        float s = q4.x * k4.x + q4.y * k4.y + q4.z * k4.z + q4.w * k4.w;
        #pragma unroll
        for (int o = 16; o; o >>= 1) s += __shfl_down_sync(0xffffffffu, s, o);
        if (lane == 0) g_diag[(size_t)bm + n] = s;
    }
    #undef FETCH
    #undef CVT_STORE
}

// ---------------------------------------------------------------------------
// Block reductions for 1024 threads (32 warps)
// ---------------------------------------------------------------------------
__device__ __forceinline__ float block_reduce_sum32(float v, float* red) {
    int lane = threadIdx.x & 31, warp = threadIdx.x >> 5;
    #pragma unroll
    for (int o = 16; o; o >>= 1) v += __shfl_down_sync(0xffffffffu, v, o);
    if (lane == 0) red[warp] = v;
    __syncthreads();
    if (warp == 0) {
        v = red[lane];
        #pragma unroll
        for (int o = 16; o; o >>= 1) v += __shfl_down_sync(0xffffffffu, v, o);
        if (lane == 0) red[32] = v;
    }
    __syncthreads();
    float r = red[32];
    __syncthreads();
    return r;
}

__device__ __forceinline__ float block_reduce_max32(float v, float* red) {
    int lane = threadIdx.x & 31, warp = threadIdx.x >> 5;
    #pragma unroll
    for (int o = 16; o; o >>= 1) v = fmaxf(v, __shfl_down_sync(0xffffffffu, v, o));
    if (lane == 0) red[warp] = v;
    __syncthreads();
    if (warp == 0) {
        v = red[lane];
        #pragma unroll
        for (int o = 16; o; o >>= 1) v = fmaxf(v, __shfl_down_sync(0xffffffffu, v, o));
        if (lane == 0) red[32] = v;
    }
    __syncthreads();
    float r = red[32];
    __syncthreads();
    return r;
}

// ---------------------------------------------------------------------------
// attn_fused: grid BATCH, 1024 threads. agg (split-d) -> softmax -> context.
// 2x warps vs round 8: halves the latency-bound agg/ctx critical paths.
// ---------------------------------------------------------------------------
__global__ __launch_bounds__(1024)
void attn_fused_kernel(const float* __restrict__ mask, float* __restrict__ out) {
    const int b = blockIdx.x, tid = threadIdx.x;
    const int lane = tid & 31, warp = tid >> 5;
    const int n = tid & 511, half = tid >> 9;      // atom, d-half
    __shared__ float qs[DIMP];
    __shared__ float agg2[2][NATOM];
    __shared__ float aw[NATOM];
    __shared__ float red[33];

    if (tid < DIMP) {
        qs[tid] = g_qsum_part[b * 4 + 0][tid] + g_qsum_part[b * 4 + 1][tid]
                + g_qsum_part[b * 4 + 2][tid] + g_qsum_part[b * 4 + 3][tid];
    }
    __syncthreads();

    const float* __restrict__ Kt = &g_Kt[b][0][0];   // [128][512]

    // agg partial: this thread sums d in [half*64, half*64+64) for atom n
    {
        float acc = 0.0f;
        const int d0 = half * 64;
        #pragma unroll 8
        for (int d = d0; d < d0 + 64; d++)
            acc = fmaf(Kt[d * NATOM + n], qs[d], acc);
        agg2[half][n] = acc;
    }
    __syncthreads();

    // combine, mask, subtract diag (valid lanes: tid < 512)
    float v = 0.0f, mv = 0.0f;
    if (tid < NATOM) {
        mv = mask[(size_t)b * NATOM + tid];
        v = mv * (agg2[0][tid] + agg2[1][tid] - g_diag[(size_t)b * NATOM + tid]);
    }

    // normalize over atoms, masked softmax (threads >= 512 contribute identity)
    const float total = block_reduce_sum32(v * v, red);
    const float nrm = sqrtf(total);
    float x = (tid < NATOM) ? (v / nrm + (1.0f - mv) * (-1e9f)) : -INFINITY;
    const float mx = block_reduce_max32(x, red);
    float e = (tid < NATOM) ? expf(x - mx) : 0.0f;
    const float denom = block_reduce_sum32(e, red);
    if (tid < NATOM) {
        const float attn = e / denom;
        out[(size_t)b * NATOM + tid] = attn;
        aw[tid] = attn * mv;
    }
    __syncthreads();

    // context[d] = sum_n aw[n] * Kt[d][n]; 32 warps x 4 d-rows
    #pragma unroll
    for (int r = 0; r < 4; r++) {
        const int d = warp * 4 + r;
        const float* row = Kt + d * NATOM;
        float s = 0.0f;
        #pragma unroll
        for (int j = 0; j < 4; j++) {
            const float4 k4 = *(const float4*)(row + j * 128 + lane * 4);
            const float4 a4 = *(const float4*)(&aw[j * 128 + lane * 4]);
            s += k4.x * a4.x + k4.y * a4.y + k4.z * a4.z + k4.w * a4.w;
        }
        #pragma unroll
        for (int o = 16; o; o >>= 1) s += __shfl_down_sync(0xffffffffu, s, o);
        if (lane == 0) out[(size_t)BATCH * NATOM + (size_t)b * DIMP + d] = s;
    }
}

// ---------------------------------------------------------------------------
extern "C" void kernel_launch(void* const* d_in, const int* in_sizes, int n_in,
                              void* d_out, int out_size) {
    const float* atom_query = (const float*)d_in[0];
    const float* mask       = (const float*)d_in[1];
    const float* Wq         = (const float*)d_in[2];
    const float* bq         = (const float*)d_in[3];
    const float* Wk         = (const float*)d_in[4];
    const float* bk         = (const float*)d_in[5];
    float* out = (float*)d_out;

    static int smem_set = 0;
    if (!smem_set) {
        cudaFuncSetAttribute(gemm_fused_kernel,
                             cudaFuncAttributeMaxDynamicSharedMemorySize, DSMEM_BYTES);
        smem_set = 1;
    }

    gemm_fused_kernel<<<NTILES, 512, DSMEM_BYTES>>>(atom_query, Wq, Wk, bq, bk, mask);
    attn_fused_kernel<<<BATCH, 1024>>>(mask, out);
}